// round 14
// baseline (speedup 1.0000x reference)
#include <cuda_runtime.h>

// Shapes: lx_in/ux_in (32768 rows x 1024 fp32), lc/uc (32768), x_min/x_max (1024).
// Outputs concatenated in d_out: [lx_out | ux_out | lc_out | uc_out].
//
// Continuation of the R3->R13 trend: 64 threads per row-block, FOUR float4
// per thread per array (8 bulk LDG.128 front-batched per thread), 2-warp
// barrier, single __syncthreads, redundant finalize, .cs streaming hints.

#define NROWS 32768
#define INNER 1024
#define NTHREADS 64
#define NWARPS (NTHREADS / 32)   // 2
#define F4 (INNER / 4)           // 256 float4 per row
#define C 4                      // float4 chunks per thread per array

__global__ __launch_bounds__(NTHREADS)
void crown_relu_64(const float* __restrict__ lx_in,
                   const float* __restrict__ ux_in,
                   const float* __restrict__ lc_in,
                   const float* __restrict__ uc_in,
                   const float* __restrict__ x_min,
                   const float* __restrict__ x_max,
                   float* __restrict__ lx_out,
                   float* __restrict__ ux_out,
                   float* __restrict__ lc_out,
                   float* __restrict__ uc_out)
{
    const int row = blockIdx.x;
    const int t   = threadIdx.x;
    const long long base4 = (long long)row * F4;

    const float4* lx4 = reinterpret_cast<const float4*>(lx_in) + base4;
    const float4* ux4 = reinterpret_cast<const float4*>(ux_in) + base4;
    const float4* mn4 = reinterpret_cast<const float4*>(x_min);
    const float4* mx4 = reinterpret_cast<const float4*>(x_max);

    // Front-batched: 8 independent streaming LDG.128 per thread.
    float4 lv[C], uv[C];
    #pragma unroll
    for (int i = 0; i < C; i++) {
        lv[i] = __ldcs(lx4 + t + i * NTHREADS);
        uv[i] = __ldcs(ux4 + t + i * NTHREADS);
    }

    // Hoisted scalar loads: latency overlaps reduction/barrier below.
    const float lc = lc_in[row];
    const float uc = uc_in[row];

    // mask_lower*lx == min(lx*mn, lx*mx); mask_upper*ux == max(...).
    float sl = 0.0f, su = 0.0f;
    #pragma unroll
    for (int i = 0; i < C; i++) {
        const float4 mn = __ldg(mn4 + t + i * NTHREADS);  // L1-hot 8KB tables
        const float4 mx = __ldg(mx4 + t + i * NTHREADS);
        sl += fminf(lv[i].x * mn.x, lv[i].x * mx.x)
            + fminf(lv[i].y * mn.y, lv[i].y * mx.y)
            + fminf(lv[i].z * mn.z, lv[i].z * mx.z)
            + fminf(lv[i].w * mn.w, lv[i].w * mx.w);
        su += fmaxf(uv[i].x * mn.x, uv[i].x * mx.x)
            + fmaxf(uv[i].y * mn.y, uv[i].y * mx.y)
            + fmaxf(uv[i].z * mn.z, uv[i].z * mx.z)
            + fmaxf(uv[i].w * mn.w, uv[i].w * mx.w);
    }

    #pragma unroll
    for (int o = 16; o > 0; o >>= 1) {
        sl += __shfl_xor_sync(0xffffffffu, sl, o);
        su += __shfl_xor_sync(0xffffffffu, su, o);
    }

    __shared__ float s_l[NWARPS];
    __shared__ float s_u[NWARPS];
    const int lane = t & 31;
    const int wid  = t >> 5;
    if (lane == 0) { s_l[wid] = sl; s_u[wid] = su; }
    __syncthreads();   // the ONLY barrier (2 warps)

    // Redundant finalize: just 2 partials each.
    const float l = lc + s_l[0] + s_l[1];
    const float u = uc + s_u[0] + s_u[1];

    const bool  alive = (l >= 0.0f);
    const bool  cross = (l < 0.0f) && (u > 0.0f);
    const float slope = cross ? fminf(fmaxf(u / (u - l), 0.0f), 1.0f) : 1.0f;

    const float fl = alive ? 1.0f : 0.0f;
    const float fu = alive ? 1.0f : (cross ? slope : 0.0f);

    if (t == 0) {
        lc_out[row] = fl * lc;
        uc_out[row] = alive ? uc : (cross ? (slope * uc - slope * l) : 0.0f);
    }

    float4* lo4 = reinterpret_cast<float4*>(lx_out) + base4;
    float4* uo4 = reinterpret_cast<float4*>(ux_out) + base4;
    #pragma unroll
    for (int i = 0; i < C; i++) {
        float4 a;
        a.x = fl * lv[i].x; a.y = fl * lv[i].y;
        a.z = fl * lv[i].z; a.w = fl * lv[i].w;
        __stcs(lo4 + t + i * NTHREADS, a);
        a.x = fu * uv[i].x; a.y = fu * uv[i].y;
        a.z = fu * uv[i].z; a.w = fu * uv[i].w;
        __stcs(uo4 + t + i * NTHREADS, a);
    }
}

extern "C" void kernel_launch(void* const* d_in, const int* in_sizes, int n_in,
                              void* d_out, int out_size)
{
    const float* lx_in = (const float*)d_in[0];
    const float* ux_in = (const float*)d_in[1];
    const float* lc_in = (const float*)d_in[2];
    const float* uc_in = (const float*)d_in[3];
    const float* x_min = (const float*)d_in[4];
    const float* x_max = (const float*)d_in[5];

    float* out = (float*)d_out;
    const long long big = (long long)NROWS * INNER;   // 33,554,432
    float* lx_out = out;
    float* ux_out = out + big;
    float* lc_out = out + 2 * big;
    float* uc_out = out + 2 * big + NROWS;

    crown_relu_64<<<NROWS, NTHREADS>>>(lx_in, ux_in, lc_in, uc_in,
                                       x_min, x_max,
                                       lx_out, ux_out, lc_out, uc_out);
}